// round 12
// baseline (speedup 1.0000x reference)
#include <cuda_runtime.h>
#include <cuda_fp16.h>
#include <cstdint>

#define N_TASKS   8
#define D_MODEL   1024
#define HIDDEN    1024
#define N_CLASSES 100
#define BATCH     8192
#define KDIM      1024
#define LDSA      72            // A smem row stride (halves)
#define LDSB      136           // B smem row stride (halves)
#define STAGES    3
#define GRID_P    296           // persistent CTAs (148 SMs x 2)

#define N_W2I     512           // W2-convert items
#define N_OUTI    800           // out-init items
#define ITEM_BASE (N_W2I + N_OUTI)

// ===================== device scratch =====================
__device__ int g_count[N_TASKS], g_offset[N_TASKS];
__device__ __align__(16) int g_rows[BATCH];
__device__ int g_mt_task[80], g_mt_m0[80], g_nmt;             // gemm1 128-row m-tiles
__device__ int g_mt2_task[160], g_mt2_m0[160], g_mt2_dep[160], g_nmt2; // gemm2 64-row m-tiles
__device__ int g_mega_ctr;
__device__ int g_done1[80];                                    // per gemm1 m-tile n-tiles done
__device__ int g_w2done, g_outdone;
__device__ __align__(256) __half g_xh[(BATCH + 128) * KDIM];
__device__ __align__(256) __half g_w1h[N_TASKS * KDIM * HIDDEN];
__device__ __align__(256) __half g_w2h[N_TASKS * KDIM * 128];
__device__ __align__(256) __half g_hh[(BATCH + 128) * KDIM];

// ===================== helpers =====================
__device__ __forceinline__ uint32_t smem_u32(const void* p) {
    uint32_t a;
    asm("{ .reg .u64 t; cvta.to.shared.u64 t, %1; cvt.u32.u64 %0, t; }" : "=r"(a) : "l"(p));
    return a;
}
__device__ __forceinline__ void ldm4(uint32_t& r0, uint32_t& r1, uint32_t& r2, uint32_t& r3,
                                     uint32_t addr) {
    asm volatile("ldmatrix.sync.aligned.m8n8.x4.shared.b16 {%0,%1,%2,%3}, [%4];"
                 : "=r"(r0), "=r"(r1), "=r"(r2), "=r"(r3) : "r"(addr));
}
__device__ __forceinline__ void ldm4t(uint32_t& r0, uint32_t& r1, uint32_t& r2, uint32_t& r3,
                                      uint32_t addr) {
    asm volatile("ldmatrix.sync.aligned.m8n8.x4.trans.shared.b16 {%0,%1,%2,%3}, [%4];"
                 : "=r"(r0), "=r"(r1), "=r"(r2), "=r"(r3) : "r"(addr));
}
__device__ __forceinline__ void mma16816(float* c, const uint32_t* a, const uint32_t* b) {
    asm volatile(
        "mma.sync.aligned.m16n8k16.row.col.f32.f16.f16.f32 "
        "{%0,%1,%2,%3}, {%4,%5,%6,%7}, {%8,%9}, {%0,%1,%2,%3};"
        : "+f"(c[0]), "+f"(c[1]), "+f"(c[2]), "+f"(c[3])
        : "r"(a[0]), "r"(a[1]), "r"(a[2]), "r"(a[3]), "r"(b[0]), "r"(b[1]));
}
__device__ __forceinline__ void cp16(uint32_t dst, const void* src) {
    asm volatile("cp.async.cg.shared.global [%0], [%1], 16;" :: "r"(dst), "l"(src) : "memory");
}
#define CP_COMMIT() asm volatile("cp.async.commit_group;" ::: "memory")
#define CP_WAIT1()  asm volatile("cp.async.wait_group 1;" ::: "memory")
#define CP_WAIT0()  asm volatile("cp.async.wait_group 0;" ::: "memory")

// ===================== grouping + tile tables (one CTA) =====================
__global__ __launch_bounds__(1024)
void group_kernel(const int* __restrict__ task_id) {
    __shared__ int cnt[N_TASKS], offs[N_TASKS], cur[N_TASKS];
    const int tid = threadIdx.x;
    if (tid < N_TASKS) { cnt[tid] = 0; cur[tid] = 0; }
    if (tid < 80) g_done1[tid] = 0;
    if (tid == 0) { g_mega_ctr = 0; g_w2done = 0; g_outdone = 0; }
    __syncthreads();
    int ids[8];
#pragma unroll
    for (int i = 0; i < 8; i++) {
        ids[i] = task_id[tid * 8 + i];
        atomicAdd(&cnt[ids[i]], 1);
    }
    __syncthreads();
    if (tid == 0) {
        int a = 0, nm = 0, nm2 = 0;
        for (int t = 0; t < N_TASKS; t++) {
            offs[t] = a; g_offset[t] = a; g_count[t] = cnt[t];
            const int base = nm;
            for (int m0 = 0; m0 < cnt[t]; m0 += 128) {
                g_mt_task[nm] = t; g_mt_m0[nm] = m0; nm++;
            }
            for (int m0 = 0; m0 < cnt[t]; m0 += 64) {
                g_mt2_task[nm2] = t; g_mt2_m0[nm2] = m0;
                g_mt2_dep[nm2] = base + (m0 >> 7);
                nm2++;
            }
            a += cnt[t];
        }
        g_nmt = nm;
        g_nmt2 = nm2;
    }
    __syncthreads();
#pragma unroll
    for (int i = 0; i < 8; i++) {
        int t = ids[i];
        int p = atomicAdd(&cur[t], 1);
        g_rows[offs[t] + p] = tid * 8 + i;
    }
}

// ===================== convert W1 + x (before mega kernel) =====================
#define W1_BLKS 4096
#define X_BLKS  2048
__global__ void convert_xw1(const float* __restrict__ x, const float* __restrict__ W1) {
    const int bid = blockIdx.x;
    const int tid = threadIdx.x;
    if (bid < W1_BLKS) {
        const size_t i = ((size_t)bid * 256 + tid) * 8;
        float4 v0 = ((const float4*)(W1 + i))[0];
        float4 v1 = ((const float4*)(W1 + i))[1];
        __half2 o[4];
        o[0] = __halves2half2(__float2half(v0.x), __float2half(v0.y));
        o[1] = __halves2half2(__float2half(v0.z), __float2half(v0.w));
        o[2] = __halves2half2(__float2half(v1.x), __float2half(v1.y));
        o[3] = __halves2half2(__float2half(v1.z), __float2half(v1.w));
        *(uint4*)(g_w1h + i) = *(uint4*)o;
    } else {
        const int lrow = tid >> 6;
        const int j    = tid & 63;
        const int b    = (bid - W1_BLKS) * 4 + lrow;
        const int r    = g_rows[b];
        const float* src = x + (size_t)r * D_MODEL + j * 16;
        float4 v0 = ((const float4*)src)[0];
        float4 v1 = ((const float4*)src)[1];
        float4 v2 = ((const float4*)src)[2];
        float4 v3 = ((const float4*)src)[3];
        __half2 o[8];
        o[0] = __halves2half2(__float2half(v0.x), __float2half(v0.y));
        o[1] = __halves2half2(__float2half(v0.z), __float2half(v0.w));
        o[2] = __halves2half2(__float2half(v1.x), __float2half(v1.y));
        o[3] = __halves2half2(__float2half(v1.z), __float2half(v1.w));
        o[4] = __halves2half2(__float2half(v2.x), __float2half(v2.y));
        o[5] = __halves2half2(__float2half(v2.z), __float2half(v2.w));
        o[6] = __halves2half2(__float2half(v3.x), __float2half(v3.y));
        o[7] = __halves2half2(__float2half(v3.z), __float2half(v3.w));
        uint4* dst = (uint4*)(g_xh + (size_t)b * KDIM + j * 16);
        dst[0] = ((uint4*)o)[0];
        dst[1] = ((uint4*)o)[1];
    }
}

// ===================== GEMM core: BM x BN tile, KCH chunks of 64 =====================
template<int BM, int BN, int BSTRIDE, int KCH>
__device__ __forceinline__ void gemm_core(
    const __half* __restrict__ gA, const __half* __restrict__ gB,
    char* smem, float c[BM / 32][BN / 32][4])
{
    constexpr int MI = BM / 32, NI = BN / 32;
    constexpr int A_BYTES = BM * LDSA * 2;
    constexpr int B_BYTES = 64 * LDSB * 2;
    constexpr int STAGE_B = A_BYTES + B_BYTES;
    constexpr int UNITS_A = BM * 8;
    constexpr int UNITS_B = 64 * (BN / 8);
    constexpr int UNITS = UNITS_A + UNITS_B;

    const int tid  = threadIdx.x;
    const int lane = tid & 31;
    const int wid  = tid >> 5;
    const int wm   = wid & 1;
    const int wn   = wid >> 1;
    const uint32_t smem0 = smem_u32(smem);

    uint32_t eA[MI], eB[NI / 2];
#pragma unroll
    for (int mi = 0; mi < MI; mi++)
        eA[mi] = ((wm * (BM / 2) + mi * 16 + (lane & 15)) * LDSA + (lane >> 4) * 8) * 2;
    {
        const int g = lane >> 3, r = lane & 7;
        const int kl = (g & 1) * 8 + r;
#pragma unroll
        for (int j = 0; j < NI / 2; j++)
            eB[j] = (kl * LDSB + wn * (BN / 4) + j * 16 + (g >> 1) * 8) * 2;
    }

    auto issue = [&](int ch, int stage) {
        const int k = ch * 64;
        const uint32_t dA = smem0 + stage * STAGE_B;
        const uint32_t dB = dA + A_BYTES;
#pragma unroll
        for (int u = tid; u < UNITS; u += 256) {
            if (u < UNITS_A) {
                int row = u >> 3, seg = u & 7;
                cp16(dA + (row * LDSA + seg * 8) * 2, gA + (size_t)row * KDIM + k + seg * 8);
            } else {
                int v = u - UNITS_A;
                int kr = v / (BN / 8), seg = v % (BN / 8);
                cp16(dB + (kr * LDSB + seg * 8) * 2, gB + (size_t)(k + kr) * BSTRIDE + seg * 8);
            }
        }
    };

    issue(0, 0); CP_COMMIT();
    issue(1, 1); CP_COMMIT();

    for (int ch = 0; ch < KCH; ch++) {
        CP_WAIT1();
        __syncthreads();
        if (ch + 2 < KCH) issue(ch + 2, (ch + 2) % STAGES);
        CP_COMMIT();

        const uint32_t bA = smem0 + (ch % STAGES) * STAGE_B;
        const uint32_t bB = bA + A_BYTES;
#pragma unroll
        for (int ks = 0; ks < 4; ks++) {
            uint32_t a[MI][4], b[NI][2];
#pragma unroll
            for (int mi = 0; mi < MI; mi++)
                ldm4(a[mi][0], a[mi][1], a[mi][2], a[mi][3], bA + eA[mi] + ks * 32);
#pragma unroll
            for (int j = 0; j < NI / 2; j++) {
                uint32_t r0, r1, r2, r3;
                ldm4t(r0, r1, r2, r3, bB + eB[j] + ks * (16 * LDSB * 2));
                b[2 * j][0] = r0; b[2 * j][1] = r1;
                b[2 * j + 1][0] = r2; b[2 * j + 1][1] = r3;
            }
#pragma unroll
            for (int mi = 0; mi < MI; mi++)
#pragma unroll
                for (int ni = 0; ni < NI; ni++)
                    mma16816(c[mi][ni], a[mi], b[ni]);
        }
    }
}

// ===================== mega kernel: W2conv | out-init | gemm1 | gemm2 =====================
#define SMEM_MEGA (STAGES * (128 * LDSA + 64 * LDSB) * 2)
__global__ __launch_bounds__(256, 2)
void mega_kernel(const float* __restrict__ W2, const int* __restrict__ task_id,
                 const float* __restrict__ b2, const float* __restrict__ b1,
                 float* __restrict__ out) {
    extern __shared__ char smem[];
    __shared__ int s_it;

    const int tid  = threadIdx.x;
    const int lane = tid & 31;
    const int wid  = tid >> 5;
    const int wm = wid & 1, wn = wid >> 1;
    const int r4 = lane >> 2, c2 = (lane & 3) * 2;

    const int n1 = g_nmt * 8;
    const int n2 = g_nmt2 * 2;
    const int ntotal = ITEM_BASE + n1 + n2;

    for (;;) {
        if (tid == 0) s_it = atomicAdd(&g_mega_ctr, 1);
        __syncthreads();
        const int it = s_it;
        if (it >= ntotal) return;

        if (it < N_W2I) {
            // ---- W2 convert item ----
            const size_t e = ((size_t)it * 256 + tid) * 8;
            const int rk = (int)(e >> 7);
            const int n0 = (int)(e & 127);
            const float* src = W2 + (size_t)rk * N_CLASSES;
            __half2 o[4];
#pragma unroll
            for (int j = 0; j < 4; j++) {
                int na = n0 + 2 * j, nb = n0 + 2 * j + 1;
                float fa = (na < N_CLASSES) ? src[na] : 0.f;
                float fb = (nb < N_CLASSES) ? src[nb] : 0.f;
                o[j] = __halves2half2(__float2half(fa), __float2half(fb));
            }
            *(uint4*)(g_w2h + (size_t)rk * 128 + n0) = *(uint4*)o;
            __threadfence();
            __syncthreads();
            if (tid == 0) atomicAdd(&g_w2done, 1);
        } else if (it < ITEM_BASE) {
            // ---- out init item: out[b][n] = b2[task[b]][n] ----
            const int e0 = ((it - N_W2I) * 256 + tid) * 4;
#pragma unroll
            for (int i = 0; i < 4; i++) {
                int e = e0 + i;
                int b = e / N_CLASSES, n = e - b * N_CLASSES;
                out[e] = b2[task_id[b] * N_CLASSES + n];
            }
            __threadfence();
            __syncthreads();
            if (tid == 0) atomicAdd(&g_outdone, 1);
        } else if (it < ITEM_BASE + n1) {
            // ---- gemm1 tile ----
            const int tile = it - ITEM_BASE;
            const int e  = tile >> 3;
            const int n0 = (tile & 7) * 128;
            const int t  = g_mt_task[e];
            const int m0 = g_mt_m0[e];
            const int cnt = g_count[t];
            const int off = g_offset[t];

            float c[4][4][4];
#pragma unroll
            for (int mi = 0; mi < 4; mi++)
#pragma unroll
                for (int ni = 0; ni < 4; ni++)
#pragma unroll
                    for (int r = 0; r < 4; r++) c[mi][ni][r] = 0.f;

            gemm_core<128, 128, HIDDEN, 16>(g_xh + (size_t)(off + m0) * KDIM,
                                            g_w1h + (size_t)t * KDIM * HIDDEN + n0, smem, c);

            const float* b1t = b1 + t * HIDDEN + n0;
#pragma unroll
            for (int mi = 0; mi < 4; mi++) {
#pragma unroll
                for (int half = 0; half < 2; half++) {
                    const int m = m0 + wm * 64 + mi * 16 + r4 + half * 8;
                    if (m < cnt) {
                        const size_t rowo = (size_t)(off + m) * KDIM;
#pragma unroll
                        for (int ni = 0; ni < 4; ni++) {
                            const int n = wn * 32 + ni * 8 + c2;
                            float v0 = fmaxf(c[mi][ni][half * 2 + 0] + b1t[n], 0.f);
                            float v1 = fmaxf(c[mi][ni][half * 2 + 1] + b1t[n + 1], 0.f);
                            *(__half2*)(g_hh + rowo + n0 + n) =
                                __halves2half2(__float2half(v0), __float2half(v1));
                        }
                    }
                }
            }
            CP_WAIT0();
            __threadfence();
            __syncthreads();
            if (tid == 0) atomicAdd(&g_done1[e], 1);
        } else {
            // ---- gemm2 tile: 64x128, split-K=2, atomic epilogue ----
            const int tile = it - ITEM_BASE - n1;
            const int e  = tile >> 1;
            const int ks = tile & 1;
            const int t  = g_mt2_task[e];
            const int m0 = g_mt2_m0[e];
            const int cnt = g_count[t];
            const int off = g_offset[t];
            const int dep = g_mt2_dep[e];

            if (tid == 0) {
                while (*(volatile int*)&g_w2done < N_W2I) {}
                while (*(volatile int*)&g_outdone < N_OUTI) {}
                while (*(volatile int*)&g_done1[dep] < 8) {}
            }
            __syncthreads();
            __threadfence();

            float c[2][4][4];
#pragma unroll
            for (int mi = 0; mi < 2; mi++)
#pragma unroll
                for (int ni = 0; ni < 4; ni++)
#pragma unroll
                    for (int r = 0; r < 4; r++) c[mi][ni][r] = 0.f;

            gemm_core<64, 128, 128, 8>(g_hh + (size_t)(off + m0) * KDIM + ks * 512,
                                       g_w2h + (size_t)t * KDIM * 128 + (size_t)ks * 512 * 128,
                                       smem, c);

#pragma unroll
            for (int mi = 0; mi < 2; mi++) {
#pragma unroll
                for (int half = 0; half < 2; half++) {
                    const int m = m0 + wm * 32 + mi * 16 + r4 + half * 8;
                    if (m < cnt) {
                        const int ro = g_rows[off + m];
                        float* orow = out + (size_t)ro * N_CLASSES;
#pragma unroll
                        for (int ni = 0; ni < 4; ni++) {
                            const int n = wn * 32 + ni * 8 + c2;
                            if (n < N_CLASSES)
                                atomicAdd(orow + n, c[mi][ni][half * 2 + 0]);
                            if (n + 1 < N_CLASSES)
                                atomicAdd(orow + n + 1, c[mi][ni][half * 2 + 1]);
                        }
                    }
                }
            }
            CP_WAIT0();
            __syncthreads();
        }
    }
}

// ===================== launch =====================
extern "C" void kernel_launch(void* const* d_in, const int* in_sizes, int n_in,
                              void* d_out, int out_size) {
    const float* x       = (const float*)d_in[0];
    const int*   task_id = (const int*)d_in[1];
    const float* W1      = (const float*)d_in[2];
    const float* b1      = (const float*)d_in[3];
    const float* W2      = (const float*)d_in[4];
    const float* b2      = (const float*)d_in[5];
    float* out = (float*)d_out;

    static bool attr_done = false;
    if (!attr_done) {
        cudaFuncSetAttribute(mega_kernel, cudaFuncAttributeMaxDynamicSharedMemorySize, SMEM_MEGA);
        attr_done = true;
    }

    group_kernel<<<1, 1024>>>(task_id);
    convert_xw1<<<W1_BLKS + X_BLKS, 256>>>(x, W1);
    mega_kernel<<<GRID_P, 256, SMEM_MEGA>>>(W2, task_id, b2, b1, out);
}

// round 13
// speedup vs baseline: 1.1165x; 1.1165x over previous
#include <cuda_runtime.h>
#include <cuda_fp16.h>
#include <cstdint>

#define N_TASKS   8
#define D_MODEL   1024
#define HIDDEN    1024
#define N_CLASSES 100
#define BATCH     8192
#define KDIM      1024
#define LDSA      72            // A smem row stride (halves)
#define LDSB      136           // B smem row stride (halves)
#define STAGES    3
#define GRID1     296
#define GRID2     296

// ===================== device scratch =====================
__device__ int g_count[N_TASKS], g_offset[N_TASKS];
__device__ __align__(16) int g_rows[BATCH];
__device__ int g_mt_task[80], g_mt_m0[80], g_nmt;       // gemm1 128-row m-tiles
__device__ int g_mt2_task[160], g_mt2_m0[160], g_nmt2;  // gemm2 64-row m-tiles
__device__ int g_tile_ctr, g_tile_ctr2;
__device__ __align__(256) __half g_xh[(BATCH + 128) * KDIM];
__device__ __align__(256) __half g_w1h[N_TASKS * KDIM * HIDDEN];
__device__ __align__(256) __half g_w2h[N_TASKS * KDIM * 128];
__device__ __align__(256) __half g_hh[(BATCH + 128) * KDIM];

// ===================== helpers =====================
__device__ __forceinline__ uint32_t smem_u32(const void* p) {
    uint32_t a;
    asm("{ .reg .u64 t; cvta.to.shared.u64 t, %1; cvt.u32.u64 %0, t; }" : "=r"(a) : "l"(p));
    return a;
}
__device__ __forceinline__ void ldm4(uint32_t& r0, uint32_t& r1, uint32_t& r2, uint32_t& r3,
                                     uint32_t addr) {
    asm volatile("ldmatrix.sync.aligned.m8n8.x4.shared.b16 {%0,%1,%2,%3}, [%4];"
                 : "=r"(r0), "=r"(r1), "=r"(r2), "=r"(r3) : "r"(addr));
}
__device__ __forceinline__ void ldm4t(uint32_t& r0, uint32_t& r1, uint32_t& r2, uint32_t& r3,
                                      uint32_t addr) {
    asm volatile("ldmatrix.sync.aligned.m8n8.x4.trans.shared.b16 {%0,%1,%2,%3}, [%4];"
                 : "=r"(r0), "=r"(r1), "=r"(r2), "=r"(r3) : "r"(addr));
}
__device__ __forceinline__ void mma16816(float* c, const uint32_t* a, const uint32_t* b) {
    asm volatile(
        "mma.sync.aligned.m16n8k16.row.col.f32.f16.f16.f32 "
        "{%0,%1,%2,%3}, {%4,%5,%6,%7}, {%8,%9}, {%0,%1,%2,%3};"
        : "+f"(c[0]), "+f"(c[1]), "+f"(c[2]), "+f"(c[3])
        : "r"(a[0]), "r"(a[1]), "r"(a[2]), "r"(a[3]), "r"(b[0]), "r"(b[1]));
}
__device__ __forceinline__ void cp16(uint32_t dst, const void* src) {
    asm volatile("cp.async.cg.shared.global [%0], [%1], 16;" :: "r"(dst), "l"(src) : "memory");
}
#define CP_COMMIT() asm volatile("cp.async.commit_group;" ::: "memory")
#define CP_WAIT1()  asm volatile("cp.async.wait_group 1;" ::: "memory")
#define CP_WAIT0()  asm volatile("cp.async.wait_group 0;" ::: "memory")

// ===================== grouping: atomic-free counting sort (one CTA) =====================
__global__ __launch_bounds__(1024)
void group_kernel(const int* __restrict__ task_id) {
    __shared__ uint64_t wlo[32], whi[32];
    __shared__ int s_off[N_TASKS];
    const int tid  = threadIdx.x;
    const int lane = tid & 31;
    const int wid  = tid >> 5;

    int ids[8];
    uint64_t lo = 0, hi = 0;          // per-thread counts, 16-bit lanes (tasks 0-3 / 4-7)
#pragma unroll
    for (int i = 0; i < 8; i++) {
        ids[i] = task_id[tid * 8 + i];
        int t = ids[i];
        if (t < 4) lo += 1ull << (t * 16);
        else       hi += 1ull << ((t - 4) * 16);
    }
    // warp inclusive scan
    uint64_t slo = lo, shi = hi;
#pragma unroll
    for (int d = 1; d < 32; d <<= 1) {
        uint64_t nlo = __shfl_up_sync(0xffffffffu, slo, d);
        uint64_t nhi = __shfl_up_sync(0xffffffffu, shi, d);
        if (lane >= d) { slo += nlo; shi += nhi; }
    }
    if (lane == 31) { wlo[wid] = slo; whi[wid] = shi; }
    __syncthreads();
    // warp 0 scans the 32 warp totals (16-bit lanes hold totals <= 8192, fits)
    if (wid == 0) {
        uint64_t a = wlo[lane], b = whi[lane];
#pragma unroll
        for (int d = 1; d < 32; d <<= 1) {
            uint64_t na = __shfl_up_sync(0xffffffffu, a, d);
            uint64_t nb = __shfl_up_sync(0xffffffffu, b, d);
            if (lane >= d) { a += na; b += nb; }
        }
        wlo[lane] = a; whi[lane] = b;
    }
    __syncthreads();
    // thread 0: offsets + tile tables + counter resets
    if (tid == 0) {
        int tot[N_TASKS];
#pragma unroll
        for (int t = 0; t < 4; t++) tot[t] = (int)((wlo[31] >> (t * 16)) & 0xffff);
#pragma unroll
        for (int t = 4; t < 8; t++) tot[t] = (int)((whi[31] >> ((t - 4) * 16)) & 0xffff);
        int a = 0, nm = 0, nm2 = 0;
        for (int t = 0; t < N_TASKS; t++) {
            s_off[t] = a; g_offset[t] = a; g_count[t] = tot[t];
            for (int m0 = 0; m0 < tot[t]; m0 += 128) { g_mt_task[nm] = t; g_mt_m0[nm] = m0; nm++; }
            for (int m0 = 0; m0 < tot[t]; m0 += 64)  { g_mt2_task[nm2] = t; g_mt2_m0[nm2] = m0; nm2++; }
            a += tot[t];
        }
        g_nmt = nm; g_nmt2 = nm2;
        g_tile_ctr = 0; g_tile_ctr2 = 0;
    }
    __syncthreads();
    // rank computation: offset + warps-before + lanes-before + within-thread-before
    const uint64_t pwlo = wid ? wlo[wid - 1] : 0ull;
    const uint64_t pwhi = wid ? whi[wid - 1] : 0ull;
    const uint64_t elo = pwlo + (slo - lo);
    const uint64_t ehi = pwhi + (shi - hi);
#pragma unroll
    for (int i = 0; i < 8; i++) {
        const int t = ids[i];
        int before = 0;
#pragma unroll
        for (int j = 0; j < 8; j++)
            if (j < i) before += (ids[j] == t);
        const uint64_t packed = (t < 4) ? elo : ehi;
        const int prior = (int)((packed >> ((t & 3) * 16)) & 0xffff);
        g_rows[s_off[t] + prior + before] = tid * 8 + i;
    }
}

// ===================== fused conversions + out init: 4 regions =====================
#define W1_BLKS 4096
#define W2_BLKS 512
#define X_BLKS  2048
#define OUT_BLKS 800
__global__ void convert_all(const float* __restrict__ x,
                            const float* __restrict__ W1,
                            const float* __restrict__ W2,
                            const int* __restrict__ task_id,
                            const float* __restrict__ b2,
                            float* __restrict__ out) {
    const int bid = blockIdx.x;
    const int tid = threadIdx.x;
    if (bid < W1_BLKS) {
        const size_t i = ((size_t)bid * 256 + tid) * 8;
        float4 v0 = ((const float4*)(W1 + i))[0];
        float4 v1 = ((const float4*)(W1 + i))[1];
        __half2 o[4];
        o[0] = __halves2half2(__float2half(v0.x), __float2half(v0.y));
        o[1] = __halves2half2(__float2half(v0.z), __float2half(v0.w));
        o[2] = __halves2half2(__float2half(v1.x), __float2half(v1.y));
        o[3] = __halves2half2(__float2half(v1.z), __float2half(v1.w));
        *(uint4*)(g_w1h + i) = *(uint4*)o;
    } else if (bid < W1_BLKS + W2_BLKS) {
        const size_t e = ((size_t)(bid - W1_BLKS) * 256 + tid) * 8;
        const int rk = (int)(e >> 7);
        const int n0 = (int)(e & 127);
        const float* src = W2 + (size_t)rk * N_CLASSES;
        __half2 o[4];
#pragma unroll
        for (int j = 0; j < 4; j++) {
            int na = n0 + 2 * j, nb = n0 + 2 * j + 1;
            float fa = (na < N_CLASSES) ? src[na] : 0.f;
            float fb = (nb < N_CLASSES) ? src[nb] : 0.f;
            o[j] = __halves2half2(__float2half(fa), __float2half(fb));
        }
        *(uint4*)(g_w2h + (size_t)rk * 128 + n0) = *(uint4*)o;
    } else if (bid < W1_BLKS + W2_BLKS + X_BLKS) {
        const int lrow = tid >> 6;
        const int j    = tid & 63;
        const int b    = (bid - W1_BLKS - W2_BLKS) * 4 + lrow;
        const int r    = g_rows[b];
        const float* src = x + (size_t)r * D_MODEL + j * 16;
        float4 v0 = ((const float4*)src)[0];
        float4 v1 = ((const float4*)src)[1];
        float4 v2 = ((const float4*)src)[2];
        float4 v3 = ((const float4*)src)[3];
        __half2 o[8];
        o[0] = __halves2half2(__float2half(v0.x), __float2half(v0.y));
        o[1] = __halves2half2(__float2half(v0.z), __float2half(v0.w));
        o[2] = __halves2half2(__float2half(v1.x), __float2half(v1.y));
        o[3] = __halves2half2(__float2half(v1.z), __float2half(v1.w));
        o[4] = __halves2half2(__float2half(v2.x), __float2half(v2.y));
        o[5] = __halves2half2(__float2half(v2.z), __float2half(v2.w));
        o[6] = __halves2half2(__float2half(v3.x), __float2half(v3.y));
        o[7] = __halves2half2(__float2half(v3.z), __float2half(v3.w));
        uint4* dst = (uint4*)(g_xh + (size_t)b * KDIM + j * 16);
        dst[0] = ((uint4*)o)[0];
        dst[1] = ((uint4*)o)[1];
    } else {
        const int e0 = ((bid - W1_BLKS - W2_BLKS - X_BLKS) * 256 + tid) * 4;
#pragma unroll
        for (int i = 0; i < 4; i++) {
            int e = e0 + i;
            int b = e / N_CLASSES, n = e - b * N_CLASSES;
            out[e] = b2[task_id[b] * N_CLASSES + n];
        }
    }
}

// ===================== GEMM core: BM x BN tile, KCH chunks of 64 =====================
template<int BM, int BN, int BSTRIDE, int KCH>
__device__ __forceinline__ void gemm_core(
    const __half* __restrict__ gA, const __half* __restrict__ gB,
    char* smem, float c[BM / 32][BN / 32][4])
{
    constexpr int MI = BM / 32, NI = BN / 32;
    constexpr int A_BYTES = BM * LDSA * 2;
    constexpr int B_BYTES = 64 * LDSB * 2;
    constexpr int STAGE_B = A_BYTES + B_BYTES;
    constexpr int UNITS_A = BM * 8;
    constexpr int UNITS_B = 64 * (BN / 8);
    constexpr int UNITS = UNITS_A + UNITS_B;

    const int tid  = threadIdx.x;
    const int lane = tid & 31;
    const int wid  = tid >> 5;
    const int wm   = wid & 1;
    const int wn   = wid >> 1;
    const uint32_t smem0 = smem_u32(smem);

    uint32_t eA[MI], eB[NI / 2];
#pragma unroll
    for (int mi = 0; mi < MI; mi++)
        eA[mi] = ((wm * (BM / 2) + mi * 16 + (lane & 15)) * LDSA + (lane >> 4) * 8) * 2;
    {
        const int g = lane >> 3, r = lane & 7;
        const int kl = (g & 1) * 8 + r;
#pragma unroll
        for (int j = 0; j < NI / 2; j++)
            eB[j] = (kl * LDSB + wn * (BN / 4) + j * 16 + (g >> 1) * 8) * 2;
    }

    auto issue = [&](int ch, int stage) {
        const int k = ch * 64;
        const uint32_t dA = smem0 + stage * STAGE_B;
        const uint32_t dB = dA + A_BYTES;
#pragma unroll
        for (int u = tid; u < UNITS; u += 256) {
            if (u < UNITS_A) {
                int row = u >> 3, seg = u & 7;
                cp16(dA + (row * LDSA + seg * 8) * 2, gA + (size_t)row * KDIM + k + seg * 8);
            } else {
                int v = u - UNITS_A;
                int kr = v / (BN / 8), seg = v % (BN / 8);
                cp16(dB + (kr * LDSB + seg * 8) * 2, gB + (size_t)(k + kr) * BSTRIDE + seg * 8);
            }
        }
    };

    issue(0, 0); CP_COMMIT();
    issue(1, 1); CP_COMMIT();

    for (int ch = 0; ch < KCH; ch++) {
        CP_WAIT1();
        __syncthreads();
        if (ch + 2 < KCH) issue(ch + 2, (ch + 2) % STAGES);
        CP_COMMIT();

        const uint32_t bA = smem0 + (ch % STAGES) * STAGE_B;
        const uint32_t bB = bA + A_BYTES;
#pragma unroll
        for (int ks = 0; ks < 4; ks++) {
            uint32_t a[MI][4], b[NI][2];
#pragma unroll
            for (int mi = 0; mi < MI; mi++)
                ldm4(a[mi][0], a[mi][1], a[mi][2], a[mi][3], bA + eA[mi] + ks * 32);
#pragma unroll
            for (int j = 0; j < NI / 2; j++) {
                uint32_t r0, r1, r2, r3;
                ldm4t(r0, r1, r2, r3, bB + eB[j] + ks * (16 * LDSB * 2));
                b[2 * j][0] = r0; b[2 * j][1] = r1;
                b[2 * j + 1][0] = r2; b[2 * j + 1][1] = r3;
            }
#pragma unroll
            for (int mi = 0; mi < MI; mi++)
#pragma unroll
                for (int ni = 0; ni < NI; ni++)
                    mma16816(c[mi][ni], a[mi], b[ni]);
        }
    }
}

// ===================== layer 1: persistent, dynamic tile queue =====================
#define SMEM1 (STAGES * (128 * LDSA + 64 * LDSB) * 2)
__global__ __launch_bounds__(256, 2)
void gemm1_mma(const float* __restrict__ b1) {
    extern __shared__ char smem[];
    __shared__ int s_tile;
    const int ntotal = g_nmt * 8;

    const int lane = threadIdx.x & 31;
    const int wid  = threadIdx.x >> 5;
    const int wm = wid & 1, wn = wid >> 1;
    const int r4 = lane >> 2, c2 = (lane & 3) * 2;

    for (;;) {
        if (threadIdx.x == 0) s_tile = atomicAdd(&g_tile_ctr, 1);
        __syncthreads();
        const int tile = s_tile;
        if (tile >= ntotal) return;
        const int e  = tile >> 3;
        const int n0 = (tile & 7) * 128;
        const int t  = g_mt_task[e];
        const int m0 = g_mt_m0[e];
        const int cnt = g_count[t];
        const int off = g_offset[t];

        float c[4][4][4];
#pragma unroll
        for (int mi = 0; mi < 4; mi++)
#pragma unroll
            for (int ni = 0; ni < 4; ni++)
#pragma unroll
                for (int r = 0; r < 4; r++) c[mi][ni][r] = 0.f;

        gemm_core<128, 128, HIDDEN, 16>(g_xh + (size_t)(off + m0) * KDIM,
                                        g_w1h + (size_t)t * KDIM * HIDDEN + n0, smem, c);

        const float* b1t = b1 + t * HIDDEN + n0;
#pragma unroll
        for (int mi = 0; mi < 4; mi++) {
#pragma unroll
            for (int half = 0; half < 2; half++) {
                const int m = m0 + wm * 64 + mi * 16 + r4 + half * 8;
                if (m < cnt) {
                    const size_t rowo = (size_t)(off + m) * KDIM;
#pragma unroll
                    for (int ni = 0; ni < 4; ni++) {
                        const int n = wn * 32 + ni * 8 + c2;
                        float v0 = fmaxf(c[mi][ni][half * 2 + 0] + b1t[n], 0.f);
                        float v1 = fmaxf(c[mi][ni][half * 2 + 1] + b1t[n + 1], 0.f);
                        *(__half2*)(g_hh + rowo + n0 + n) =
                            __halves2half2(__float2half(v0), __float2half(v1));
                    }
                }
            }
        }
        CP_WAIT0();
        __syncthreads();
    }
}

// ===================== layer 2: persistent, 64x128, split-K=2 (one wave), atomic =====================
#define SMEM2 (STAGES * (64 * LDSA + 64 * LDSB) * 2)
__global__ __launch_bounds__(256, 2)
void gemm2_mma(float* __restrict__ out) {
    extern __shared__ char smem[];
    __shared__ int s_tile;
    const int ntotal = g_nmt2 * 2;

    const int lane = threadIdx.x & 31;
    const int wid  = threadIdx.x >> 5;
    const int wm = wid & 1, wn = wid >> 1;
    const int r4 = lane >> 2, c2 = (lane & 3) * 2;

    for (;;) {
        if (threadIdx.x == 0) s_tile = atomicAdd(&g_tile_ctr2, 1);
        __syncthreads();
        const int tile = s_tile;
        if (tile >= ntotal) return;
        const int e  = tile >> 1;
        const int ks = tile & 1;              // K-split: [ks*512, ks*512+512)
        const int t  = g_mt2_task[e];
        const int m0 = g_mt2_m0[e];
        const int cnt = g_count[t];
        const int off = g_offset[t];

        float c[2][4][4];
#pragma unroll
        for (int mi = 0; mi < 2; mi++)
#pragma unroll
            for (int ni = 0; ni < 4; ni++)
#pragma unroll
                for (int r = 0; r < 4; r++) c[mi][ni][r] = 0.f;

        gemm_core<64, 128, 128, 8>(g_hh + (size_t)(off + m0) * KDIM + ks * 512,
                                   g_w2h + (size_t)t * KDIM * 128 + (size_t)ks * 512 * 128,
                                   smem, c);

#pragma unroll
        for (int mi = 0; mi < 2; mi++) {
#pragma unroll
            for (int half = 0; half < 2; half++) {
                const int m = m0 + wm * 32 + mi * 16 + r4 + half * 8;
                if (m < cnt) {
                    const int ro = g_rows[off + m];
                    float* orow = out + (size_t)ro * N_CLASSES;
#pragma unroll
                    for (int ni = 0; ni < 4; ni++) {
                        const int n = wn * 32 + ni * 8 + c2;
                        if (n < N_CLASSES)
                            atomicAdd(orow + n, c[mi][ni][half * 2 + 0]);
                        if (n + 1 < N_CLASSES)
                            atomicAdd(orow + n + 1, c[mi][ni][half * 2 + 1]);
                    }
                }
            }
        }
        CP_WAIT0();
        __syncthreads();
    }
}

// ===================== launch =====================
extern "C" void kernel_launch(void* const* d_in, const int* in_sizes, int n_in,
                              void* d_out, int out_size) {
    const float* x       = (const float*)d_in[0];
    const int*   task_id = (const int*)d_in[1];
    const float* W1      = (const float*)d_in[2];
    const float* b1      = (const float*)d_in[3];
    const float* W2      = (const float*)d_in[4];
    const float* b2      = (const float*)d_in[5];
    float* out = (float*)d_out;

    static bool attr_done = false;
    if (!attr_done) {
        cudaFuncSetAttribute(gemm1_mma, cudaFuncAttributeMaxDynamicSharedMemorySize, SMEM1);
        cudaFuncSetAttribute(gemm2_mma, cudaFuncAttributeMaxDynamicSharedMemorySize, SMEM2);
        attr_done = true;
    }

    group_kernel<<<1, 1024>>>(task_id);
    convert_all<<<W1_BLKS + W2_BLKS + X_BLKS + OUT_BLKS, 256>>>(x, W1, W2, task_id, b2, out);

    gemm1_mma<<<GRID1, 256, SMEM1>>>(b1);
    gemm2_mma<<<GRID2, 256, SMEM2>>>(out);
}

// round 14
// speedup vs baseline: 1.1454x; 1.0259x over previous
#include <cuda_runtime.h>
#include <cuda_fp16.h>
#include <cstdint>

#define N_TASKS   8
#define D_MODEL   1024
#define HIDDEN    1024
#define N_CLASSES 100
#define BATCH     8192
#define KDIM      1024
#define LDSA      72
#define LDSB      136
#define GRID1     296
#define GRID2     296

// ===================== device scratch =====================
__device__ int g_count[N_TASKS], g_offset[N_TASKS];
__device__ __align__(16) int g_rows[BATCH];
__device__ int g_mt_task[80], g_mt_m0[80], g_nmt;
__device__ int g_mt2_task[160], g_mt2_m0[160], g_nmt2;
__device__ int g_tile_ctr, g_tile_ctr2;
__device__ __align__(256) __half g_xh[BATCH * KDIM];              // UNGROUPED x fp16
__device__ __align__(256) __half g_w1h[N_TASKS * KDIM * HIDDEN];
__device__ __align__(256) __half g_w2h[N_TASKS * KDIM * 128];
__device__ __align__(256) __half g_hh[(BATCH + 128) * KDIM];      // grouped h fp16

// ===================== helpers =====================
__device__ __forceinline__ uint32_t smem_u32(const void* p) {
    uint32_t a;
    asm("{ .reg .u64 t; cvta.to.shared.u64 t, %1; cvt.u32.u64 %0, t; }" : "=r"(a) : "l"(p));
    return a;
}
__device__ __forceinline__ void ldm4(uint32_t& r0, uint32_t& r1, uint32_t& r2, uint32_t& r3,
                                     uint32_t addr) {
    asm volatile("ldmatrix.sync.aligned.m8n8.x4.shared.b16 {%0,%1,%2,%3}, [%4];"
                 : "=r"(r0), "=r"(r1), "=r"(r2), "=r"(r3) : "r"(addr));
}
__device__ __forceinline__ void ldm4t(uint32_t& r0, uint32_t& r1, uint32_t& r2, uint32_t& r3,
                                      uint32_t addr) {
    asm volatile("ldmatrix.sync.aligned.m8n8.x4.trans.shared.b16 {%0,%1,%2,%3}, [%4];"
                 : "=r"(r0), "=r"(r1), "=r"(r2), "=r"(r3) : "r"(addr));
}
__device__ __forceinline__ void mma16816(float* c, const uint32_t* a, const uint32_t* b) {
    asm volatile(
        "mma.sync.aligned.m16n8k16.row.col.f32.f16.f16.f32 "
        "{%0,%1,%2,%3}, {%4,%5,%6,%7}, {%8,%9}, {%0,%1,%2,%3};"
        : "+f"(c[0]), "+f"(c[1]), "+f"(c[2]), "+f"(c[3])
        : "r"(a[0]), "r"(a[1]), "r"(a[2]), "r"(a[3]), "r"(b[0]), "r"(b[1]));
}
__device__ __forceinline__ void cp16(uint32_t dst, const void* src) {
    asm volatile("cp.async.cg.shared.global [%0], [%1], 16;" :: "r"(dst), "l"(src) : "memory");
}
#define CP_COMMIT() asm volatile("cp.async.commit_group;" ::: "memory")
#define CP_WAIT0()  asm volatile("cp.async.wait_group 0;" ::: "memory")
template<int N> __device__ __forceinline__ void cp_wait() {
    asm volatile("cp.async.wait_group %0;" :: "n"(N) : "memory");
}

// ===================== fused convert + group: 5 regions =====================
#define GRP_BLKS 1
#define W1_BLKS  4096
#define W2_BLKS  512
#define X_BLKS   2048
#define OUT_BLKS 800
__global__ __launch_bounds__(256)
void convert_all(const float* __restrict__ x,
                 const float* __restrict__ W1,
                 const float* __restrict__ W2,
                 const int* __restrict__ task_id,
                 const float* __restrict__ b2,
                 float* __restrict__ out) {
    const int bid = blockIdx.x;
    const int tid = threadIdx.x;
    if (bid == 0) {
        // ---- grouping: atomic-free counting sort, 256 threads x 32 elems ----
        __shared__ uint64_t wlo[8], whi[8];
        __shared__ int s_off[N_TASKS];
        const int lane = tid & 31;
        const int wid  = tid >> 5;
        int ids[32];
        uint64_t lo = 0, hi = 0;
#pragma unroll
        for (int i = 0; i < 32; i++) {
            ids[i] = task_id[tid * 32 + i];
            int t = ids[i];
            if (t < 4) lo += 1ull << (t * 16);
            else       hi += 1ull << ((t - 4) * 16);
        }
        uint64_t slo = lo, shi = hi;
#pragma unroll
        for (int d = 1; d < 32; d <<= 1) {
            uint64_t nlo = __shfl_up_sync(0xffffffffu, slo, d);
            uint64_t nhi = __shfl_up_sync(0xffffffffu, shi, d);
            if (lane >= d) { slo += nlo; shi += nhi; }
        }
        if (lane == 31) { wlo[wid] = slo; whi[wid] = shi; }
        __syncthreads();
        if (wid == 0 && lane < 8) {
            uint64_t a = wlo[lane], b = whi[lane];
#pragma unroll
            for (int d = 1; d < 8; d <<= 1) {
                uint64_t na = __shfl_up_sync(0xffu, a, d);
                uint64_t nb = __shfl_up_sync(0xffu, b, d);
                if (lane >= d) { a += na; b += nb; }
            }
            wlo[lane] = a; whi[lane] = b;
        }
        __syncthreads();
        if (tid == 0) {
            int tot[N_TASKS];
#pragma unroll
            for (int t = 0; t < 4; t++) tot[t] = (int)((wlo[7] >> (t * 16)) & 0xffff);
#pragma unroll
            for (int t = 4; t < 8; t++) tot[t] = (int)((whi[7] >> ((t - 4) * 16)) & 0xffff);
            int a = 0, nm = 0, nm2 = 0;
            for (int t = 0; t < N_TASKS; t++) {
                s_off[t] = a; g_offset[t] = a; g_count[t] = tot[t];
                for (int m0 = 0; m0 < tot[t]; m0 += 128) { g_mt_task[nm] = t; g_mt_m0[nm] = m0; nm++; }
                for (int m0 = 0; m0 < tot[t]; m0 += 64)  { g_mt2_task[nm2] = t; g_mt2_m0[nm2] = m0; nm2++; }
                a += tot[t];
            }
            g_nmt = nm; g_nmt2 = nm2;
            g_tile_ctr = 0; g_tile_ctr2 = 0;
        }
        __syncthreads();
        uint64_t elo = (wid ? wlo[wid - 1] : 0ull) + (slo - lo);
        uint64_t ehi = (wid ? whi[wid - 1] : 0ull) + (shi - hi);
#pragma unroll
        for (int i = 0; i < 32; i++) {
            const int t = ids[i];
            const int sh = (t & 3) * 16;
            int prior;
            if (t < 4) { prior = (int)((elo >> sh) & 0xffff); elo += 1ull << sh; }
            else       { prior = (int)((ehi >> sh) & 0xffff); ehi += 1ull << sh; }
            g_rows[s_off[t] + prior] = tid * 32 + i;
        }
    } else if (bid < GRP_BLKS + W1_BLKS) {
        const size_t i = ((size_t)(bid - GRP_BLKS) * 256 + tid) * 8;
        float4 v0 = ((const float4*)(W1 + i))[0];
        float4 v1 = ((const float4*)(W1 + i))[1];
        __half2 o[4];
        o[0] = __halves2half2(__float2half(v0.x), __float2half(v0.y));
        o[1] = __halves2half2(__float2half(v0.z), __float2half(v0.w));
        o[2] = __halves2half2(__float2half(v1.x), __float2half(v1.y));
        o[3] = __halves2half2(__float2half(v1.z), __float2half(v1.w));
        *(uint4*)(g_w1h + i) = *(uint4*)o;
    } else if (bid < GRP_BLKS + W1_BLKS + W2_BLKS) {
        const size_t e = ((size_t)(bid - GRP_BLKS - W1_BLKS) * 256 + tid) * 8;
        const int rk = (int)(e >> 7);
        const int n0 = (int)(e & 127);
        const float* src = W2 + (size_t)rk * N_CLASSES;
        __half2 o[4];
#pragma unroll
        for (int j = 0; j < 4; j++) {
            int na = n0 + 2 * j, nb = n0 + 2 * j + 1;
            float fa = (na < N_CLASSES) ? src[na] : 0.f;
            float fb = (nb < N_CLASSES) ? src[nb] : 0.f;
            o[j] = __halves2half2(__float2half(fa), __float2half(fb));
        }
        *(uint4*)(g_w2h + (size_t)rk * 128 + n0) = *(uint4*)o;
    } else if (bid < GRP_BLKS + W1_BLKS + W2_BLKS + X_BLKS) {
        // x: pure streaming (UNGROUPED), 16 floats/thread
        const size_t i = ((size_t)(bid - GRP_BLKS - W1_BLKS - W2_BLKS) * 256 + tid) * 16;
        float4 v0 = ((const float4*)(x + i))[0];
        float4 v1 = ((const float4*)(x + i))[1];
        float4 v2 = ((const float4*)(x + i))[2];
        float4 v3 = ((const float4*)(x + i))[3];
        __half2 o[8];
        o[0] = __halves2half2(__float2half(v0.x), __float2half(v0.y));
        o[1] = __halves2half2(__float2half(v0.z), __float2half(v0.w));
        o[2] = __halves2half2(__float2half(v1.x), __float2half(v1.y));
        o[3] = __halves2half2(__float2half(v1.z), __float2half(v1.w));
        o[4] = __halves2half2(__float2half(v2.x), __float2half(v2.y));
        o[5] = __halves2half2(__float2half(v2.z), __float2half(v2.w));
        o[6] = __halves2half2(__float2half(v3.x), __float2half(v3.y));
        o[7] = __halves2half2(__float2half(v3.z), __float2half(v3.w));
        uint4* dst = (uint4*)(g_xh + i);
        dst[0] = ((uint4*)o)[0];
        dst[1] = ((uint4*)o)[1];
    } else {
        const int e0 = ((bid - GRP_BLKS - W1_BLKS - W2_BLKS - X_BLKS) * 256 + tid) * 4;
#pragma unroll
        for (int i = 0; i < 4; i++) {
            int e = e0 + i;
            int b = e / N_CLASSES, n = e - b * N_CLASSES;
            out[e] = b2[task_id[b] * N_CLASSES + n];
        }
    }
}

// ===================== GEMM core =====================
template<int BM, int BN, int BSTRIDE, int KCH, int NSTAGES, bool GATHER>
__device__ __forceinline__ void gemm_core(
    const __half* __restrict__ gA, const int* __restrict__ s_rows,
    const __half* __restrict__ gB,
    char* smem, float c[BM / 32][BN / 32][4])
{
    constexpr int MI = BM / 32, NI = BN / 32;
    constexpr int A_BYTES = BM * LDSA * 2;
    constexpr int B_BYTES = 64 * LDSB * 2;
    constexpr int STAGE_B = A_BYTES + B_BYTES;
    constexpr int UNITS_A = BM * 8;
    constexpr int UNITS_B = 64 * (BN / 8);
    constexpr int UNITS = UNITS_A + UNITS_B;

    const int tid  = threadIdx.x;
    const int lane = tid & 31;
    const int wid  = tid >> 5;
    const int wm   = wid & 1;
    const int wn   = wid >> 1;
    const uint32_t smem0 = smem_u32(smem);

    uint32_t eA[MI], eB[NI / 2];
#pragma unroll
    for (int mi = 0; mi < MI; mi++)
        eA[mi] = ((wm * (BM / 2) + mi * 16 + (lane & 15)) * LDSA + (lane >> 4) * 8) * 2;
    {
        const int g = lane >> 3, r = lane & 7;
        const int kl = (g & 1) * 8 + r;
#pragma unroll
        for (int j = 0; j < NI / 2; j++)
            eB[j] = (kl * LDSB + wn * (BN / 4) + j * 16 + (g >> 1) * 8) * 2;
    }

    auto issue = [&](int ch, int stage) {
        const int k = ch * 64;
        const uint32_t dA = smem0 + stage * STAGE_B;
        const uint32_t dB = dA + A_BYTES;
#pragma unroll
        for (int u = tid; u < UNITS; u += 256) {
            if (u < UNITS_A) {
                int row = u >> 3, seg = u & 7;
                size_t srow = GATHER ? (size_t)s_rows[row] : (size_t)row;
                cp16(dA + (row * LDSA + seg * 8) * 2, gA + srow * KDIM + k + seg * 8);
            } else {
                int v = u - UNITS_A;
                int kr = v / (BN / 8), seg = v % (BN / 8);
                cp16(dB + (kr * LDSB + seg * 8) * 2, gB + (size_t)(k + kr) * BSTRIDE + seg * 8);
            }
        }
    };

#pragma unroll
    for (int s = 0; s < NSTAGES - 1; s++) { issue(s, s); CP_COMMIT(); }

    for (int ch = 0; ch < KCH; ch++) {
        cp_wait<NSTAGES - 2>();
        __syncthreads();
        if (ch + NSTAGES - 1 < KCH) issue(ch + NSTAGES - 1, (ch + NSTAGES - 1) % NSTAGES);
        CP_COMMIT();

        const uint32_t bA = smem0 + (ch % NSTAGES) * STAGE_B;
        const uint32_t bB = bA + A_BYTES;
#pragma unroll
        for (int ks = 0; ks < 4; ks++) {
            uint32_t a[MI][4], b[NI][2];
#pragma unroll
            for (int mi = 0; mi < MI; mi++)
                ldm4(a[mi][0], a[mi][1], a[mi][2], a[mi][3], bA + eA[mi] + ks * 32);
#pragma unroll
            for (int j = 0; j < NI / 2; j++) {
                uint32_t r0, r1, r2, r3;
                ldm4t(r0, r1, r2, r3, bB + eB[j] + ks * (16 * LDSB * 2));
                b[2 * j][0] = r0; b[2 * j][1] = r1;
                b[2 * j + 1][0] = r2; b[2 * j + 1][1] = r3;
            }
#pragma unroll
            for (int mi = 0; mi < MI; mi++)
#pragma unroll
                for (int ni = 0; ni < NI; ni++)
                    mma16816(c[mi][ni], a[mi], b[ni]);
        }
    }
}

// ===================== layer 1: persistent, gather A =====================
#define STG1 3
#define SMEM1 (STG1 * (128 * LDSA + 64 * LDSB) * 2 + 512)
__global__ __launch_bounds__(256, 2)
void gemm1_mma(const float* __restrict__ b1) {
    extern __shared__ char smem[];
    int* s_rows = (int*)(smem + STG1 * (128 * LDSA + 64 * LDSB) * 2);
    __shared__ int s_tile;
    const int ntotal = g_nmt * 8;

    const int lane = threadIdx.x & 31;
    const int wid  = threadIdx.x >> 5;
    const int wm = wid & 1, wn = wid >> 1;
    const int r4 = lane >> 2, c2 = (lane & 3) * 2;

    for (;;) {
        if (threadIdx.x == 0) s_tile = atomicAdd(&g_tile_ctr, 1);
        __syncthreads();
        const int tile = s_tile;
        if (tile >= ntotal) return;
        const int e  = tile >> 3;
        const int n0 = (tile & 7) * 128;
        const int t  = g_mt_task[e];
        const int m0 = g_mt_m0[e];
        const int cnt = g_count[t];
        const int off = g_offset[t];

        if (threadIdx.x < 128) {
            int m = m0 + threadIdx.x;
            int idx = off + ((m < cnt) ? m : (cnt - 1));
            s_rows[threadIdx.x] = g_rows[idx];
        }
        __syncthreads();

        float c[4][4][4];
#pragma unroll
        for (int mi = 0; mi < 4; mi++)
#pragma unroll
            for (int ni = 0; ni < 4; ni++)
#pragma unroll
                for (int r = 0; r < 4; r++) c[mi][ni][r] = 0.f;

        gemm_core<128, 128, HIDDEN, 16, STG1, true>(
            g_xh, s_rows, g_w1h + (size_t)t * KDIM * HIDDEN + n0, smem, c);

        const float* b1t = b1 + t * HIDDEN + n0;
#pragma unroll
        for (int mi = 0; mi < 4; mi++) {
#pragma unroll
            for (int half = 0; half < 2; half++) {
                const int m = m0 + wm * 64 + mi * 16 + r4 + half * 8;
                if (m < cnt) {
                    const size_t rowo = (size_t)(off + m) * KDIM;
#pragma unroll
                    for (int ni = 0; ni < 4; ni++) {
                        const int n = wn * 32 + ni * 8 + c2;
                        float v0 = fmaxf(c[mi][ni][half * 2 + 0] + b1t[n], 0.f);
                        float v1 = fmaxf(c[mi][ni][half * 2 + 1] + b1t[n + 1], 0.f);
                        *(__half2*)(g_hh + rowo + n0 + n) =
                            __halves2half2(__float2half(v0), __float2half(v1));
                    }
                }
            }
        }
        CP_WAIT0();
        __syncthreads();
    }
}

// ===================== layer 2: persistent, 64x128, split-K=2, 4 stages =====================
#define STG2 4
#define SMEM2 (STG2 * (64 * LDSA + 64 * LDSB) * 2)
__global__ __launch_bounds__(256, 2)
void gemm2_mma(float* __restrict__ out) {
    extern __shared__ char smem[];
    __shared__ int s_tile;
    const int ntotal = g_nmt2 * 2;

    const int lane = threadIdx.x & 31;
    const int wid  = threadIdx.x >> 5;
    const int wm = wid & 1, wn = wid >> 1;
    const int r4 = lane >> 2, c2 = (lane & 3) * 2;

    for (;;) {
        if (threadIdx.x == 0) s_tile = atomicAdd(&g_tile_ctr2, 1);
        __syncthreads();
        const int tile = s_tile;
        if (tile >= ntotal) return;
        const int e  = tile >> 1;
        const int ks = tile & 1;
        const int t  = g_mt2_task[e];
        const int m0 = g_mt2_m0[e];
        const int cnt = g_count[t];
        const int off = g_offset[t];

        float c[2][4][4];
#pragma unroll
        for (int mi = 0; mi < 2; mi++)
#pragma unroll
            for (int ni = 0; ni < 4; ni++)
#pragma unroll
                for (int r = 0; r < 4; r++) c[mi][ni][r] = 0.f;

        gemm_core<64, 128, 128, 8, STG2, false>(
            g_hh + (size_t)(off + m0) * KDIM + ks * 512, nullptr,
            g_w2h + (size_t)t * KDIM * 128 + (size_t)ks * 512 * 128, smem, c);

#pragma unroll
        for (int mi = 0; mi < 2; mi++) {
#pragma unroll
            for (int half = 0; half < 2; half++) {
                const int m = m0 + wm * 32 + mi * 16 + r4 + half * 8;
                if (m < cnt) {
                    const int ro = g_rows[off + m];
                    float* orow = out + (size_t)ro * N_CLASSES;
#pragma unroll
                    for (int ni = 0; ni < 4; ni++) {
                        const int n = wn * 32 + ni * 8 + c2;
                        if (n < N_CLASSES)
                            atomicAdd(orow + n, c[mi][ni][half * 2 + 0]);
                        if (n + 1 < N_CLASSES)
                            atomicAdd(orow + n + 1, c[mi][ni][half * 2 + 1]);
                    }
                }
            }
        }
        CP_WAIT0();
        __syncthreads();
    }
}

// ===================== launch =====================
extern "C" void kernel_launch(void* const* d_in, const int* in_sizes, int n_in,
                              void* d_out, int out_size) {
    const float* x       = (const float*)d_in[0];
    const int*   task_id = (const int*)d_in[1];
    const float* W1      = (const float*)d_in[2];
    const float* b1      = (const float*)d_in[3];
    const float* W2      = (const float*)d_in[4];
    const float* b2      = (const float*)d_in[5];
    float* out = (float*)d_out;

    static bool attr_done = false;
    if (!attr_done) {
        cudaFuncSetAttribute(gemm1_mma, cudaFuncAttributeMaxDynamicSharedMemorySize, SMEM1);
        cudaFuncSetAttribute(gemm2_mma, cudaFuncAttributeMaxDynamicSharedMemorySize, SMEM2);
        attr_done = true;
    }

    convert_all<<<GRP_BLKS + W1_BLKS + W2_BLKS + X_BLKS + OUT_BLKS, 256>>>(
        x, W1, W2, task_id, b2, out);
    gemm1_mma<<<GRID1, 256, SMEM1>>>(b1);
    gemm2_mma<<<GRID2, 256, SMEM2>>>(out);
}

// round 15
// speedup vs baseline: 1.1461x; 1.0006x over previous
#include <cuda_runtime.h>
#include <cuda_fp16.h>
#include <cstdint>

#define N_TASKS   8
#define D_MODEL   1024
#define HIDDEN    1024
#define N_CLASSES 100
#define BATCH     8192
#define KDIM      1024
#define LDSA      72
#define LDSB      136
#define LDSH      136            // h-tile staging row stride (halves)
#define GRID1     296
#define GRID2     296

// ===================== device scratch =====================
__device__ int g_count[N_TASKS], g_offset[N_TASKS];
__device__ __align__(16) int g_rows[BATCH];
__device__ int g_mt_task[80], g_mt_m0[80], g_nmt;
__device__ int g_mt2_task[160], g_mt2_m0[160], g_nmt2;
__device__ int g_tile_ctr, g_tile_ctr2;
__device__ __align__(256) __half g_xh[BATCH * KDIM];              // ungrouped x fp16
__device__ __align__(256) __half g_w1h[N_TASKS * KDIM * HIDDEN];
__device__ __align__(256) __half g_w2h[N_TASKS * KDIM * 128];
__device__ __align__(256) __half g_hh[(BATCH + 128) * KDIM];      // grouped h fp16

// ===================== helpers =====================
__device__ __forceinline__ uint32_t smem_u32(const void* p) {
    uint32_t a;
    asm("{ .reg .u64 t; cvta.to.shared.u64 t, %1; cvt.u32.u64 %0, t; }" : "=r"(a) : "l"(p));
    return a;
}
__device__ __forceinline__ void ldm4(uint32_t& r0, uint32_t& r1, uint32_t& r2, uint32_t& r3,
                                     uint32_t addr) {
    asm volatile("ldmatrix.sync.aligned.m8n8.x4.shared.b16 {%0,%1,%2,%3}, [%4];"
                 : "=r"(r0), "=r"(r1), "=r"(r2), "=r"(r3) : "r"(addr));
}
__device__ __forceinline__ void ldm4t(uint32_t& r0, uint32_t& r1, uint32_t& r2, uint32_t& r3,
                                      uint32_t addr) {
    asm volatile("ldmatrix.sync.aligned.m8n8.x4.trans.shared.b16 {%0,%1,%2,%3}, [%4];"
                 : "=r"(r0), "=r"(r1), "=r"(r2), "=r"(r3) : "r"(addr));
}
__device__ __forceinline__ void mma16816(float* c, const uint32_t* a, const uint32_t* b) {
    asm volatile(
        "mma.sync.aligned.m16n8k16.row.col.f32.f16.f16.f32 "
        "{%0,%1,%2,%3}, {%4,%5,%6,%7}, {%8,%9}, {%0,%1,%2,%3};"
        : "+f"(c[0]), "+f"(c[1]), "+f"(c[2]), "+f"(c[3])
        : "r"(a[0]), "r"(a[1]), "r"(a[2]), "r"(a[3]), "r"(b[0]), "r"(b[1]));
}
__device__ __forceinline__ void cp16(uint32_t dst, const void* src) {
    asm volatile("cp.async.cg.shared.global [%0], [%1], 16;" :: "r"(dst), "l"(src) : "memory");
}
#define CP_COMMIT() asm volatile("cp.async.commit_group;" ::: "memory")
#define CP_WAIT0()  asm volatile("cp.async.wait_group 0;" ::: "memory")
template<int N> __device__ __forceinline__ void cp_wait() {
    asm volatile("cp.async.wait_group %0;" :: "n"(N) : "memory");
}

// ===================== fused convert + group: 5 regions =====================
#define GRP_BLKS 1
#define W1_BLKS  4096
#define W2_BLKS  512
#define X_BLKS   2048
#define OUT_BLKS 800
__global__ __launch_bounds__(256)
void convert_all(const float* __restrict__ x,
                 const float* __restrict__ W1,
                 const float* __restrict__ W2,
                 const int* __restrict__ task_id,
                 const float* __restrict__ b2,
                 float* __restrict__ out) {
    const int bid = blockIdx.x;
    const int tid = threadIdx.x;
    if (bid == 0) {
        // ---- grouping: counting sort, no per-thread id cache (low regs) ----
        __shared__ uint64_t wlo[8], whi[8];
        __shared__ int s_off[N_TASKS];
        const int lane = tid & 31;
        const int wid  = tid >> 5;
        uint64_t lo = 0, hi = 0;
#pragma unroll 4
        for (int i = 0; i < 32; i++) {
            int t = task_id[tid * 32 + i];
            if (t < 4) lo += 1ull << (t * 16);
            else       hi += 1ull << ((t - 4) * 16);
        }
        uint64_t slo = lo, shi = hi;
#pragma unroll
        for (int d = 1; d < 32; d <<= 1) {
            uint64_t nlo = __shfl_up_sync(0xffffffffu, slo, d);
            uint64_t nhi = __shfl_up_sync(0xffffffffu, shi, d);
            if (lane >= d) { slo += nlo; shi += nhi; }
        }
        if (lane == 31) { wlo[wid] = slo; whi[wid] = shi; }
        __syncthreads();
        if (wid == 0 && lane < 8) {
            uint64_t a = wlo[lane], b = whi[lane];
#pragma unroll
            for (int d = 1; d < 8; d <<= 1) {
                uint64_t na = __shfl_up_sync(0xffu, a, d);
                uint64_t nb = __shfl_up_sync(0xffu, b, d);
                if (lane >= d) { a += na; b += nb; }
            }
            wlo[lane] = a; whi[lane] = b;
        }
        __syncthreads();
        if (tid == 0) {
            int tot[N_TASKS];
#pragma unroll
            for (int t = 0; t < 4; t++) tot[t] = (int)((wlo[7] >> (t * 16)) & 0xffff);
#pragma unroll
            for (int t = 4; t < 8; t++) tot[t] = (int)((whi[7] >> ((t - 4) * 16)) & 0xffff);
            int a = 0, nm = 0, nm2 = 0;
            for (int t = 0; t < N_TASKS; t++) {
                s_off[t] = a; g_offset[t] = a; g_count[t] = tot[t];
                for (int m0 = 0; m0 < tot[t]; m0 += 128) { g_mt_task[nm] = t; g_mt_m0[nm] = m0; nm++; }
                for (int m0 = 0; m0 < tot[t]; m0 += 64)  { g_mt2_task[nm2] = t; g_mt2_m0[nm2] = m0; nm2++; }
                a += tot[t];
            }
            g_nmt = nm; g_nmt2 = nm2;
            g_tile_ctr = 0; g_tile_ctr2 = 0;
        }
        __syncthreads();
        uint64_t elo = (wid ? wlo[wid - 1] : 0ull) + (slo - lo);
        uint64_t ehi = (wid ? whi[wid - 1] : 0ull) + (shi - hi);
#pragma unroll 4
        for (int i = 0; i < 32; i++) {
            const int t = task_id[tid * 32 + i];    // re-read (L2-hot)
            const int sh = (t & 3) * 16;
            int prior;
            if (t < 4) { prior = (int)((elo >> sh) & 0xffff); elo += 1ull << sh; }
            else       { prior = (int)((ehi >> sh) & 0xffff); ehi += 1ull << sh; }
            g_rows[s_off[t] + prior] = tid * 32 + i;
        }
    } else if (bid < GRP_BLKS + W1_BLKS) {
        const size_t i = ((size_t)(bid - GRP_BLKS) * 256 + tid) * 8;
        float4 v0 = ((const float4*)(W1 + i))[0];
        float4 v1 = ((const float4*)(W1 + i))[1];
        __half2 o[4];
        o[0] = __halves2half2(__float2half(v0.x), __float2half(v0.y));
        o[1] = __halves2half2(__float2half(v0.z), __float2half(v0.w));
        o[2] = __halves2half2(__float2half(v1.x), __float2half(v1.y));
        o[3] = __halves2half2(__float2half(v1.z), __float2half(v1.w));
        *(uint4*)(g_w1h + i) = *(uint4*)o;
    } else if (bid < GRP_BLKS + W1_BLKS + W2_BLKS) {
        const size_t e = ((size_t)(bid - GRP_BLKS - W1_BLKS) * 256 + tid) * 8;
        const int rk = (int)(e >> 7);
        const int n0 = (int)(e & 127);
        const float* src = W2 + (size_t)rk * N_CLASSES;
        __half2 o[4];
#pragma unroll
        for (int j = 0; j < 4; j++) {
            int na = n0 + 2 * j, nb = n0 + 2 * j + 1;
            float fa = (na < N_CLASSES) ? src[na] : 0.f;
            float fb = (nb < N_CLASSES) ? src[nb] : 0.f;
            o[j] = __halves2half2(__float2half(fa), __float2half(fb));
        }
        *(uint4*)(g_w2h + (size_t)rk * 128 + n0) = *(uint4*)o;
    } else if (bid < GRP_BLKS + W1_BLKS + W2_BLKS + X_BLKS) {
        const size_t i = ((size_t)(bid - GRP_BLKS - W1_BLKS - W2_BLKS) * 256 + tid) * 16;
        float4 v0 = ((const float4*)(x + i))[0];
        float4 v1 = ((const float4*)(x + i))[1];
        float4 v2 = ((const float4*)(x + i))[2];
        float4 v3 = ((const float4*)(x + i))[3];
        __half2 o[8];
        o[0] = __halves2half2(__float2half(v0.x), __float2half(v0.y));
        o[1] = __halves2half2(__float2half(v0.z), __float2half(v0.w));
        o[2] = __halves2half2(__float2half(v1.x), __float2half(v1.y));
        o[3] = __halves2half2(__float2half(v1.z), __float2half(v1.w));
        o[4] = __halves2half2(__float2half(v2.x), __float2half(v2.y));
        o[5] = __halves2half2(__float2half(v2.z), __float2half(v2.w));
        o[6] = __halves2half2(__float2half(v3.x), __float2half(v3.y));
        o[7] = __halves2half2(__float2half(v3.z), __float2half(v3.w));
        uint4* dst = (uint4*)(g_xh + i);
        dst[0] = ((uint4*)o)[0];
        dst[1] = ((uint4*)o)[1];
    } else {
        const int e0 = ((bid - GRP_BLKS - W1_BLKS - W2_BLKS - X_BLKS) * 256 + tid) * 4;
#pragma unroll
        for (int i = 0; i < 4; i++) {
            int e = e0 + i;
            int b = e / N_CLASSES, n = e - b * N_CLASSES;
            out[e] = b2[task_id[b] * N_CLASSES + n];
        }
    }
}

// ===================== GEMM core =====================
template<int BM, int BN, int BSTRIDE, int KCH, int NSTAGES, bool GATHER>
__device__ __forceinline__ void gemm_core(
    const __half* __restrict__ gA, const int* __restrict__ s_rows,
    const __half* __restrict__ gB,
    char* smem, float c[BM / 32][BN / 32][4])
{
    constexpr int MI = BM / 32, NI = BN / 32;
    constexpr int A_BYTES = BM * LDSA * 2;
    constexpr int B_BYTES = 64 * LDSB * 2;
    constexpr int STAGE_B = A_BYTES + B_BYTES;
    constexpr int UNITS_A = BM * 8;
    constexpr int UNITS_B = 64 * (BN / 8);
    constexpr int UNITS = UNITS_A + UNITS_B;

    const int tid  = threadIdx.x;
    const int lane = tid & 31;
    const int wid  = tid >> 5;
    const int wm   = wid & 1;
    const int wn   = wid >> 1;
    const uint32_t smem0 = smem_u32(smem);

    uint32_t eA[MI], eB[NI / 2];
#pragma unroll
    for (int mi = 0; mi < MI; mi++)
        eA[mi] = ((wm * (BM / 2) + mi * 16 + (lane & 15)) * LDSA + (lane >> 4) * 8) * 2;
    {
        const int g = lane >> 3, r = lane & 7;
        const int kl = (g & 1) * 8 + r;
#pragma unroll
        for (int j = 0; j < NI / 2; j++)
            eB[j] = (kl * LDSB + wn * (BN / 4) + j * 16 + (g >> 1) * 8) * 2;
    }

    auto issue = [&](int ch, int stage) {
        const int k = ch * 64;
        const uint32_t dA = smem0 + stage * STAGE_B;
        const uint32_t dB = dA + A_BYTES;
#pragma unroll
        for (int u = tid; u < UNITS; u += 256) {
            if (u < UNITS_A) {
                int row = u >> 3, seg = u & 7;
                size_t srow = GATHER ? (size_t)s_rows[row] : (size_t)row;
                cp16(dA + (row * LDSA + seg * 8) * 2, gA + srow * KDIM + k + seg * 8);
            } else {
                int v = u - UNITS_A;
                int kr = v / (BN / 8), seg = v % (BN / 8);
                cp16(dB + (kr * LDSB + seg * 8) * 2, gB + (size_t)(k + kr) * BSTRIDE + seg * 8);
            }
        }
    };

#pragma unroll
    for (int s = 0; s < NSTAGES - 1; s++) { issue(s, s); CP_COMMIT(); }

    for (int ch = 0; ch < KCH; ch++) {
        cp_wait<NSTAGES - 2>();
        __syncthreads();
        if (ch + NSTAGES - 1 < KCH) issue(ch + NSTAGES - 1, (ch + NSTAGES - 1) % NSTAGES);
        CP_COMMIT();

        const uint32_t bA = smem0 + (ch % NSTAGES) * STAGE_B;
        const uint32_t bB = bA + A_BYTES;
#pragma unroll
        for (int ks = 0; ks < 4; ks++) {
            uint32_t a[MI][4], b[NI][2];
#pragma unroll
            for (int mi = 0; mi < MI; mi++)
                ldm4(a[mi][0], a[mi][1], a[mi][2], a[mi][3], bA + eA[mi] + ks * 32);
#pragma unroll
            for (int j = 0; j < NI / 2; j++) {
                uint32_t r0, r1, r2, r3;
                ldm4t(r0, r1, r2, r3, bB + eB[j] + ks * (16 * LDSB * 2));
                b[2 * j][0] = r0; b[2 * j][1] = r1;
                b[2 * j + 1][0] = r2; b[2 * j + 1][1] = r3;
            }
#pragma unroll
            for (int mi = 0; mi < MI; mi++)
#pragma unroll
                for (int ni = 0; ni < NI; ni++)
                    mma16816(c[mi][ni], a[mi], b[ni]);
        }
    }
}

// ===================== layer 1: persistent, gather A, staged h store =====================
#define STG1 3
#define SMEM1 (STG1 * (128 * LDSA + 64 * LDSB) * 2 + 512)
__global__ __launch_bounds__(256, 2)
void gemm1_mma(const float* __restrict__ b1) {
    extern __shared__ char smem[];
    int* s_rows = (int*)(smem + STG1 * (128 * LDSA + 64 * LDSB) * 2);
    __half* hbuf = (__half*)smem;          // reuses stage space post-drain (128*LDSH*2 = 34.8KB)
    __shared__ int s_tile;
    const int ntotal = g_nmt * 8;

    const int tid  = threadIdx.x;
    const int lane = tid & 31;
    const int wid  = tid >> 5;
    const int wm = wid & 1, wn = wid >> 1;
    const int r4 = lane >> 2, c2 = (lane & 3) * 2;

    for (;;) {
        if (tid == 0) s_tile = atomicAdd(&g_tile_ctr, 1);
        __syncthreads();
        const int tile = s_tile;
        if (tile >= ntotal) return;
        const int e  = tile >> 3;
        const int n0 = (tile & 7) * 128;
        const int t  = g_mt_task[e];
        const int m0 = g_mt_m0[e];
        const int cnt = g_count[t];
        const int off = g_offset[t];

        if (tid < 128) {
            int m = m0 + tid;
            int idx = off + ((m < cnt) ? m : (cnt - 1));
            s_rows[tid] = g_rows[idx];
        }
        __syncthreads();

        float c[4][4][4];
#pragma unroll
        for (int mi = 0; mi < 4; mi++)
#pragma unroll
            for (int ni = 0; ni < 4; ni++)
#pragma unroll
                for (int r = 0; r < 4; r++) c[mi][ni][r] = 0.f;

        gemm_core<128, 128, HIDDEN, 16, STG1, true>(
            g_xh, s_rows, g_w1h + (size_t)t * KDIM * HIDDEN + n0, smem, c);

        // drain pipeline, then reuse stage smem as h-tile buffer
        CP_WAIT0();
        __syncthreads();

        const float* b1t = b1 + t * HIDDEN + n0;
#pragma unroll
        for (int mi = 0; mi < 4; mi++) {
#pragma unroll
            for (int half = 0; half < 2; half++) {
                const int row = wm * 64 + mi * 16 + r4 + half * 8;
#pragma unroll
                for (int ni = 0; ni < 4; ni++) {
                    const int n = wn * 32 + ni * 8 + c2;
                    float v0 = fmaxf(c[mi][ni][half * 2 + 0] + b1t[n], 0.f);
                    float v1 = fmaxf(c[mi][ni][half * 2 + 1] + b1t[n + 1], 0.f);
                    *(__half2*)(hbuf + row * LDSH + n) =
                        __halves2half2(__float2half(v0), __float2half(v1));
                }
            }
        }
        __syncthreads();

        // coalesced 16B h stores
#pragma unroll
        for (int u = tid; u < 2048; u += 256) {
            const int row = u >> 4, seg = u & 15;
            const int m = m0 + row;
            if (m < cnt)
                *(uint4*)(g_hh + (size_t)(off + m) * KDIM + n0 + seg * 8) =
                    *(const uint4*)(hbuf + row * LDSH + seg * 8);
        }
        __syncthreads();   // protect hbuf before next tile's cp.async
    }
}

// ===================== layer 2: persistent, 64x128, split-K=2, 4 stages =====================
#define STG2 4
#define SMEM2 (STG2 * (64 * LDSA + 64 * LDSB) * 2)
__global__ __launch_bounds__(256, 2)
void gemm2_mma(float* __restrict__ out) {
    extern __shared__ char smem[];
    __shared__ int s_tile;
    const int ntotal = g_nmt2 * 2;

    const int lane = threadIdx.x & 31;
    const int wid  = threadIdx.x >> 5;
    const int wm = wid & 1, wn = wid >> 1;
    const int r4 = lane >> 2, c2 = (lane & 3) * 2;

    for (;;) {
        if (threadIdx.x == 0) s_tile = atomicAdd(&g_tile_ctr2, 1);
        __syncthreads();
        const int tile = s_tile;
        if (tile >= ntotal) return;
        const int e  = tile >> 1;
        const int ks = tile & 1;
        const int t  = g_mt2_task[e];
        const int m0 = g_mt2_m0[e];
        const int cnt = g_count[t];
        const int off = g_offset[t];

        float c[2][4][4];
#pragma unroll
        for (int mi = 0; mi < 2; mi++)
#pragma unroll
            for (int ni = 0; ni < 4; ni++)
#pragma unroll
                for (int r = 0; r < 4; r++) c[mi][ni][r] = 0.f;

        gemm_core<64, 128, 128, 8, STG2, false>(
            g_hh + (size_t)(off + m0) * KDIM + ks * 512, nullptr,
            g_w2h + (size_t)t * KDIM * 128 + (size_t)ks * 512 * 128, smem, c);

#pragma unroll
        for (int mi = 0; mi < 2; mi++) {
#pragma unroll
            for (int half = 0; half < 2; half++) {
                const int m = m0 + wm * 32 + mi * 16 + r4 + half * 8;
                if (m < cnt) {
                    const int ro = g_rows[off + m];
                    float* orow = out + (size_t)ro * N_CLASSES;
#pragma unroll
                    for (int ni = 0; ni < 4; ni++) {
                        const int n = wn * 32 + ni * 8 + c2;
                        if (n < N_CLASSES)
                            atomicAdd(orow + n, c[mi][ni][half * 2 + 0]);
                        if (n + 1 < N_CLASSES)
                            atomicAdd(orow + n + 1, c[mi][ni][half * 2 + 1]);
                    }
                }
            }
        }
        CP_WAIT0();
        __syncthreads();
    }
}

// ===================== launch =====================
extern "C" void kernel_launch(void* const* d_in, const int* in_sizes, int n_in,
                              void* d_out, int out_size) {
    const float* x       = (const float*)d_in[0];
    const int*   task_id = (const int*)d_in[1];
    const float* W1      = (const float*)d_in[2];
    const float* b1      = (const float*)d_in[3];
    const float* W2      = (const float*)d_in[4];
    const float* b2      = (const float*)d_in[5];
    float* out = (float*)d_out;

    static bool attr_done = false;
    if (!attr_done) {
        cudaFuncSetAttribute(gemm1_mma, cudaFuncAttributeMaxDynamicSharedMemorySize, SMEM1);
        cudaFuncSetAttribute(gemm2_mma, cudaFuncAttributeMaxDynamicSharedMemorySize, SMEM2);
        attr_done = true;
    }

    convert_all<<<GRP_BLKS + W1_BLKS + W2_BLKS + X_BLKS + OUT_BLKS, 256>>>(
        x, W1, W2, task_id, b2, out);
    gemm1_mma<<<GRID1, 256, SMEM1>>>(b1);
    gemm2_mma<<<GRID2, 256, SMEM2>>>(out);
}